// round 7
// baseline (speedup 1.0000x reference)
#include <cuda_runtime.h>
#include <cstdint>

// EdgeModel: out[e,:] = relu([src,dest,attr,u[batch]] @ W1 + b1) @ W2 + b2
// E = 8e6, B = 4096, W1:(4,10), W2:(10,19). Output [E,19] f32.
//
// R6 changes vs R5 (214us, L1tex 84% = bottleneck):
//  - TMA bulk store (cp.async.bulk shared->global) flushes the 38,912B output
//    tile in ONE op per CTA: removes tile readback (38 wf) + STG (38 wf) per
//    warp-pass from the L1 path entirely.
//  - 4 edges/thread (2 packed pairs), TPB=128: weight LDS wavefronts per edge
//    halved (loaded once, applied to both pairs).
//  - __launch_bounds__(128,5): 5 CTAs/SM (smem-limited), reg cap 102.
// Kept: packed f32x2 math, duplicated {w,w} smem weights, W2 transposed for
// LDS.128, 512x19 smem output tile, runtime batch-dtype detection.

#define TPB 128
#define EDGES_PER_BLOCK 512   // TPB * 4
#define PAIRS_PER_BLOCK 256   // TPB * 2
#define TILE_BYTES 38912      // 512 * 19 * 4

typedef unsigned long long u64;

__device__ int g_batch_is64;   // 1 if batch is int64, 0 if int32

__device__ __forceinline__ u64 pack2(float lo, float hi) {
    u64 r;
    asm("mov.b64 %0, {%1, %2};" : "=l"(r) : "f"(lo), "f"(hi));
    return r;
}

__device__ __forceinline__ void unpack2(u64 v, float& lo, float& hi) {
    asm("mov.b64 {%0, %1}, %2;" : "=f"(lo), "=f"(hi) : "l"(v));
}

__device__ __forceinline__ u64 fma2(u64 a, u64 b, u64 c) {
    u64 d;
    asm("fma.rn.f32x2 %0, %1, %2, %3;" : "=l"(d) : "l"(a), "l"(b), "l"(c));
    return d;
}

__device__ __forceinline__ u64 relu2(u64 v) {
    float lo, hi;
    unpack2(v, lo, hi);
    lo = fmaxf(lo, 0.0f);
    hi = fmaxf(hi, 0.0f);
    return pack2(lo, hi);
}

// Detect batch dtype: int64 with values 0..4095 -> every odd int32 word is 0.
// 1024 random int32 in [0,4096) all being zero: impossible in practice.
__global__ void detect_batch_dtype(const int* __restrict__ b32) {
    if (threadIdx.x == 0) {
        int all_zero = 1;
        for (int i = 1; i < 2048; i += 2) {
            if (b32[i] != 0) { all_zero = 0; break; }
        }
        g_batch_is64 = all_zero;
    }
}

__global__ __launch_bounds__(TPB, 5)
void edge_model_kernel(const float* __restrict__ src,
                       const float* __restrict__ dest,
                       const float* __restrict__ ea,
                       const float* __restrict__ u,
                       const void*  __restrict__ batch_raw,
                       const float* __restrict__ W1,   // [4,10]
                       const float* __restrict__ b1,   // [10]
                       const float* __restrict__ W2,   // [10,19]
                       const float* __restrict__ b2,   // [19]
                       float* __restrict__ out,        // [E,19]
                       long long E)
{
    __shared__ u64 w1p[40];                 // w1p[c*10+k] = {W1[c][k]}x2
    __shared__ u64 b1p[10];
    __shared__ __align__(16) u64 w2p[190];  // w2p[j*10+k] = {W2[k][j]}x2 (transposed)
    __shared__ u64 b2p[19];
    __shared__ __align__(16) float otile[EDGES_PER_BLOCK * 19];  // 38912 B

    const int t = threadIdx.x;
    const int is64 = g_batch_is64;

    // ---- stage weights (once per block) ----
    if (t < 40)              w1p[t] = pack2(W1[t], W1[t]);
    if (t >= 64 && t < 74)   b1p[t - 64] = pack2(b1[t - 64], b1[t - 64]);
    if (t >= 96 && t < 115)  b2p[t - 96] = pack2(b2[t - 96], b2[t - 96]);
    for (int i = t; i < 190; i += TPB) {
        int j = i / 10, k = i - j * 10;     // transpose
        float w = W2[k * 19 + j];
        w2p[i] = pack2(w, w);
    }
    __syncthreads();

    const long long base = (long long)blockIdx.x * EDGES_PER_BLOCK;

    if (base + EDGES_PER_BLOCK <= E) {
        // ============== fast path: full 512-edge block, 4 edges/thread ==============
        const long long P = base >> 1;             // first pair of block
        const long long p0 = P + t;                // pair A
        const long long p1 = P + TPB + t;          // pair B

        const float2 s0 = ((const float2*)src)[p0];
        const float2 d0 = ((const float2*)dest)[p0];
        const float2 a0 = ((const float2*)ea)[p0];
        const float2 s1 = ((const float2*)src)[p1];
        const float2 d1 = ((const float2*)dest)[p1];
        const float2 a1 = ((const float2*)ea)[p1];

        long long i00, i01, i10, i11;
        if (is64) {
            longlong2 q0 = ((const longlong2*)batch_raw)[p0];
            longlong2 q1 = ((const longlong2*)batch_raw)[p1];
            i00 = q0.x; i01 = q0.y; i10 = q1.x; i11 = q1.y;
        } else {
            int2 q0 = ((const int2*)batch_raw)[p0];
            int2 q1 = ((const int2*)batch_raw)[p1];
            i00 = q0.x; i01 = q0.y; i10 = q1.x; i11 = q1.y;
        }
        const u64 up0 = pack2(__ldg(&u[i00]), __ldg(&u[i01]));
        const u64 up1 = pack2(__ldg(&u[i10]), __ldg(&u[i11]));

        const u64 sp0 = pack2(s0.x, s0.y), sp1 = pack2(s1.x, s1.y);
        const u64 dp0 = pack2(d0.x, d0.y), dp1 = pack2(d1.x, d1.y);
        const u64 ap0 = pack2(a0.x, a0.y), ap1 = pack2(a1.x, a1.y);

        // layer 1 for both pairs (weights loaded once)
        u64 h0[10], h1[10];
        #pragma unroll
        for (int k = 0; k < 10; k++) {
            const u64 wa = w1p[k],      wb = w1p[10 + k];
            const u64 wc = w1p[20 + k], wd = w1p[30 + k];
            const u64 bb = b1p[k];
            u64 acc0 = bb, acc1 = bb;
            acc0 = fma2(sp0, wa, acc0);  acc1 = fma2(sp1, wa, acc1);
            acc0 = fma2(dp0, wb, acc0);  acc1 = fma2(dp1, wb, acc1);
            acc0 = fma2(ap0, wc, acc0);  acc1 = fma2(ap1, wc, acc1);
            acc0 = fma2(up0, wd, acc0);  acc1 = fma2(up1, wd, acc1);
            h0[k] = relu2(acc0);
            h1[k] = relu2(acc1);
        }

        // layer 2 into smem output tile (weights loaded once per j, used 2x)
        float* r0a = &otile[(2 * t)           * 19];
        float* r0b = &otile[(2 * t + 1)       * 19];
        float* r1a = &otile[(2 * (TPB + t))     * 19];
        float* r1b = &otile[(2 * (TPB + t) + 1) * 19];
        #pragma unroll 2
        for (int j = 0; j < 19; j++) {
            const u64 bb = b2p[j];
            u64 acc0 = bb, acc1 = bb;
            const ulonglong2* wr = (const ulonglong2*)&w2p[j * 10];  // 16B aligned
            #pragma unroll
            for (int kk = 0; kk < 5; kk++) {
                ulonglong2 w = wr[kk];
                acc0 = fma2(h0[2 * kk],     w.x, acc0);
                acc0 = fma2(h0[2 * kk + 1], w.y, acc0);
                acc1 = fma2(h1[2 * kk],     w.x, acc1);
                acc1 = fma2(h1[2 * kk + 1], w.y, acc1);
            }
            float lo, hi;
            unpack2(acc0, lo, hi);
            r0a[j] = lo; r0b[j] = hi;
            unpack2(acc1, lo, hi);
            r1a[j] = lo; r1b[j] = hi;
        }
        __syncthreads();

        // One TMA bulk store flushes the whole tile (no L1 wavefronts).
        if (t == 0) {
            unsigned saddr = (unsigned)__cvta_generic_to_shared(otile);
            const float* g = out + base * 19;   // byte offset multiple of 16
            asm volatile("fence.proxy.async.shared::cta;" ::: "memory");
            asm volatile(
                "cp.async.bulk.global.shared::cta.bulk_group [%0], [%1], %2;"
                :: "l"(g), "r"(saddr), "r"((unsigned)TILE_BYTES) : "memory");
            asm volatile("cp.async.bulk.commit_group;" ::: "memory");
            asm volatile("cp.async.bulk.wait_group 0;" ::: "memory");
        }
    } else {
        // ================= tail path (scalar, bounds-checked) =================
        for (long long e = base + t; e < E; e += TPB) {
            float x0 = src[e], x1 = dest[e], x2 = ea[e];
            long long bi = is64 ? ((const long long*)batch_raw)[e]
                                : (long long)((const int*)batch_raw)[e];
            float x3 = u[bi];
            float h[10];
            #pragma unroll
            for (int k = 0; k < 10; k++) {
                float acc = b1[k];
                acc = fmaf(x0, W1[k],      acc);
                acc = fmaf(x1, W1[10 + k], acc);
                acc = fmaf(x2, W1[20 + k], acc);
                acc = fmaf(x3, W1[30 + k], acc);
                h[k] = fmaxf(acc, 0.0f);
            }
            #pragma unroll
            for (int j = 0; j < 19; j++) {
                float acc = b2[j];
                #pragma unroll
                for (int k = 0; k < 10; k++)
                    acc = fmaf(h[k], W2[k * 19 + j], acc);
                out[e * 19 + j] = acc;
            }
        }
    }
}

extern "C" void kernel_launch(void* const* d_in, const int* in_sizes, int n_in,
                              void* d_out, int out_size)
{
    const float* src   = (const float*)d_in[0];
    const float* dest  = (const float*)d_in[1];
    const float* ea    = (const float*)d_in[2];
    const float* u     = (const float*)d_in[3];
    const void*  batch = d_in[4];
    const float* W1    = (const float*)d_in[5];
    const float* b1    = (const float*)d_in[6];
    const float* W2    = (const float*)d_in[7];
    const float* b2    = (const float*)d_in[8];
    float* out = (float*)d_out;

    const long long E = in_sizes[0];
    const int blocks = (int)((E + EDGES_PER_BLOCK - 1) / EDGES_PER_BLOCK);

    detect_batch_dtype<<<1, 32>>>((const int*)batch);
    edge_model_kernel<<<blocks, TPB>>>(src, dest, ea, u, batch,
                                       W1, b1, W2, b2, out, E);
}

// round 8
// speedup vs baseline: 1.2196x; 1.2196x over previous
#include <cuda_runtime.h>
#include <cstdint>

// EdgeModel: out[e,:] = relu([src,dest,attr,u[batch]] @ W1 + b1) @ W2 + b2
// E = 8e6, B = 4096, W1:(4,10), W2:(10,19). Output [E,19] f32.
//
// R7 changes vs R6 (220us, L1tex 82% bound by weight-LDS + STS wavefronts):
//  - Weights moved to __constant__ memory: prep kernel builds the duplicated
//    {w,w} / transposed pack in a __device__ scratch, one D2D
//    cudaMemcpyToSymbolAsync moves it to the constant bank. All weight/bias
//    reads become ULDC/LDC on the constant port -> zero L1tex wavefronts.
//  - Shared memory now holds ONLY the 512x19 output tile (38.9KB).
//  - Back to TPB=256, 2 edges/thread, __launch_bounds__(256,3) (R5's 24-warp
//    occupancy point; weight amortization no longer needs 4 edges/thread).
// Kept: packed f32x2 math, 512x19 smem tile + TMA bulk store, batch dtype
// detection.

#define TPB 256
#define EDGES_PER_BLOCK 512   // TPB * 2
#define TILE_BYTES 38912      // 512 * 19 * 4

typedef unsigned long long u64;

__device__ int g_batch_is64;   // 1 if batch is int64, 0 if int32

struct CWPack {
    u64 w1p[40];    // {W1[c][k]}x2, index c*10+k
    u64 b1p[10];    // {b1[k]}x2
    u64 w2p[190];   // {W2[k][j]}x2 transposed, index j*10+k  (16B-aligned rows)
    u64 b2p[19];    // {b2[j]}x2
    u64 pad;
};

__device__ CWPack g_wscratch;      // staging (written by prep kernel)
__constant__ CWPack c_w;           // read-only broadcast copy

__device__ __forceinline__ u64 pack2(float lo, float hi) {
    u64 r;
    asm("mov.b64 %0, {%1, %2};" : "=l"(r) : "f"(lo), "f"(hi));
    return r;
}

__device__ __forceinline__ void unpack2(u64 v, float& lo, float& hi) {
    asm("mov.b64 {%0, %1}, %2;" : "=f"(lo), "=f"(hi) : "l"(v));
}

__device__ __forceinline__ u64 fma2(u64 a, u64 b, u64 c) {
    u64 d;
    asm("fma.rn.f32x2 %0, %1, %2, %3;" : "=l"(d) : "l"(a), "l"(b), "l"(c));
    return d;
}

__device__ __forceinline__ u64 relu2(u64 v) {
    float lo, hi;
    unpack2(v, lo, hi);
    lo = fmaxf(lo, 0.0f);
    hi = fmaxf(hi, 0.0f);
    return pack2(lo, hi);
}

// Detect batch dtype: int64 with values 0..4095 -> every odd int32 word is 0.
__global__ void detect_batch_dtype(const int* __restrict__ b32) {
    if (threadIdx.x == 0) {
        int all_zero = 1;
        for (int i = 1; i < 2048; i += 2) {
            if (b32[i] != 0) { all_zero = 0; break; }
        }
        g_batch_is64 = all_zero;
    }
}

// Build the duplicated/transposed weight pack in device scratch.
__global__ void prep_weights(const float* __restrict__ W1,
                             const float* __restrict__ b1,
                             const float* __restrict__ W2,
                             const float* __restrict__ b2)
{
    int t = threadIdx.x;
    if (t < 40)             g_wscratch.w1p[t]      = pack2(W1[t], W1[t]);
    if (t >= 64 && t < 74)  g_wscratch.b1p[t - 64] = pack2(b1[t - 64], b1[t - 64]);
    if (t >= 96 && t < 115) g_wscratch.b2p[t - 96] = pack2(b2[t - 96], b2[t - 96]);
    if (t < 190) {
        int j = t / 10, k = t - j * 10;   // transpose
        float w = W2[k * 19 + j];
        g_wscratch.w2p[t] = pack2(w, w);
    }
    if (t == 255) g_wscratch.pad = 0;
}

__global__ __launch_bounds__(TPB, 3)
void edge_model_kernel(const float* __restrict__ src,
                       const float* __restrict__ dest,
                       const float* __restrict__ ea,
                       const float* __restrict__ u,
                       const void*  __restrict__ batch_raw,
                       float* __restrict__ out,        // [E,19]
                       long long E)
{
    __shared__ __align__(16) float otile[EDGES_PER_BLOCK * 19];  // 38912 B

    const int t = threadIdx.x;
    const int is64 = g_batch_is64;

    const long long base = (long long)blockIdx.x * EDGES_PER_BLOCK;

    if (base + EDGES_PER_BLOCK <= E) {
        // ============== fast path: full 512-edge block, 2 edges/thread ==============
        const long long p = (base >> 1) + t;   // pair index

        const float2 s = ((const float2*)src)[p];
        const float2 d = ((const float2*)dest)[p];
        const float2 a = ((const float2*)ea)[p];

        long long i0, i1;
        if (is64) {
            longlong2 bi = ((const longlong2*)batch_raw)[p];
            i0 = bi.x; i1 = bi.y;
        } else {
            int2 bi = ((const int2*)batch_raw)[p];
            i0 = bi.x; i1 = bi.y;
        }
        const float u0 = __ldg(&u[i0]);
        const float u1 = __ldg(&u[i1]);

        const u64 sp = pack2(s.x, s.y);
        const u64 dp = pack2(d.x, d.y);
        const u64 ap = pack2(a.x, a.y);
        const u64 up = pack2(u0, u1);

        // layer 1 (weights from constant bank — no L1 traffic)
        u64 h[10];
        #pragma unroll
        for (int k = 0; k < 10; k++) {
            u64 acc = c_w.b1p[k];
            acc = fma2(sp, c_w.w1p[k],      acc);
            acc = fma2(dp, c_w.w1p[10 + k], acc);
            acc = fma2(ap, c_w.w1p[20 + k], acc);
            acc = fma2(up, c_w.w1p[30 + k], acc);
            h[k] = relu2(acc);
        }

        // layer 2 into smem output tile
        float* row0 = &otile[(2 * t)     * 19];
        float* row1 = &otile[(2 * t + 1) * 19];
        #pragma unroll 2
        for (int j = 0; j < 19; j++) {
            u64 acc = c_w.b2p[j];
            const ulonglong2* wr = (const ulonglong2*)&c_w.w2p[j * 10];  // 16B aligned
            #pragma unroll
            for (int kk = 0; kk < 5; kk++) {
                ulonglong2 w = wr[kk];
                acc = fma2(h[2 * kk],     w.x, acc);
                acc = fma2(h[2 * kk + 1], w.y, acc);
            }
            float lo, hi;
            unpack2(acc, lo, hi);
            row0[j] = lo;
            row1[j] = hi;
        }
        __syncthreads();

        // One TMA bulk store flushes the whole tile.
        if (t == 0) {
            unsigned saddr = (unsigned)__cvta_generic_to_shared(otile);
            const float* g = out + base * 19;   // 16B-aligned
            asm volatile("fence.proxy.async.shared::cta;" ::: "memory");
            asm volatile(
                "cp.async.bulk.global.shared::cta.bulk_group [%0], [%1], %2;"
                :: "l"(g), "r"(saddr), "r"((unsigned)TILE_BYTES) : "memory");
            asm volatile("cp.async.bulk.commit_group;" ::: "memory");
            asm volatile("cp.async.bulk.wait_group 0;" ::: "memory");
        }
    } else {
        // ================= tail path (scalar, bounds-checked) =================
        for (long long e = base + t; e < E; e += TPB) {
            float x0 = src[e], x1 = dest[e], x2 = ea[e];
            long long bi = is64 ? ((const long long*)batch_raw)[e]
                                : (long long)((const int*)batch_raw)[e];
            float x3 = u[bi];
            float h[10];
            #pragma unroll
            for (int k = 0; k < 10; k++) {
                float lo, hiu;
                unpack2(c_w.w1p[k], lo, hiu);       float wa = lo;
                unpack2(c_w.w1p[10 + k], lo, hiu);  float wb = lo;
                unpack2(c_w.w1p[20 + k], lo, hiu);  float wc = lo;
                unpack2(c_w.w1p[30 + k], lo, hiu);  float wd = lo;
                unpack2(c_w.b1p[k], lo, hiu);
                float acc = lo;
                acc = fmaf(x0, wa, acc);
                acc = fmaf(x1, wb, acc);
                acc = fmaf(x2, wc, acc);
                acc = fmaf(x3, wd, acc);
                h[k] = fmaxf(acc, 0.0f);
            }
            #pragma unroll
            for (int j = 0; j < 19; j++) {
                float lo, hiu;
                unpack2(c_w.b2p[j], lo, hiu);
                float acc = lo;
                #pragma unroll
                for (int k = 0; k < 10; k++) {
                    unpack2(c_w.w2p[j * 10 + k], lo, hiu);
                    acc = fmaf(h[k], lo, acc);
                }
                out[e * 19 + j] = acc;
            }
        }
    }
}

extern "C" void kernel_launch(void* const* d_in, const int* in_sizes, int n_in,
                              void* d_out, int out_size)
{
    const float* src   = (const float*)d_in[0];
    const float* dest  = (const float*)d_in[1];
    const float* ea    = (const float*)d_in[2];
    const float* u     = (const float*)d_in[3];
    const void*  batch = d_in[4];
    const float* W1    = (const float*)d_in[5];
    const float* b1    = (const float*)d_in[6];
    const float* W2    = (const float*)d_in[7];
    const float* b2    = (const float*)d_in[8];
    float* out = (float*)d_out;

    const long long E = in_sizes[0];
    const int blocks = (int)((E + EDGES_PER_BLOCK - 1) / EDGES_PER_BLOCK);

    detect_batch_dtype<<<1, 32>>>((const int*)batch);
    prep_weights<<<1, 256>>>(W1, b1, W2, b2);

    void* scratch_addr = nullptr;
    cudaGetSymbolAddress(&scratch_addr, g_wscratch);
    cudaMemcpyToSymbolAsync(c_w, scratch_addr, sizeof(CWPack), 0,
                            cudaMemcpyDeviceToDevice, 0);

    edge_model_kernel<<<blocks, TPB>>>(src, dest, ea, u, batch, out, E);
}

// round 9
// speedup vs baseline: 1.2307x; 1.0091x over previous
#include <cuda_runtime.h>
#include <cstdint>

// EdgeModel: out[e,:] = relu([src,dest,attr,u[batch]] @ W1 + b1) @ W2 + b2
// E = 8e6, B = 4096, W1:(4,10), W2:(10,19). Output [E,19] f32.
//
// R8 changes vs R7 (180us):
//  - Tile stores re-paired into st.shared.v2.f32 (consecutive j, same edge,
//    via a 1-element register carry): 38 2-way-conflicted STS.32 -> 20
//    conflict-free STS (u64 lane stride 19 = odd). ~76 -> ~22 L1 wavefronts
//    per warp-pass on the store side.
//  - batch-dtype detection folded into prep_weights (parallel + ballot):
//    removes the 4.5us serial detect launch from every graph replay.
// Kept: constant-bank weight pack (ULDC, zero L1), packed f32x2 math,
// 512x19 smem tile + TMA bulk store, __launch_bounds__(256,3).

#define TPB 256
#define EDGES_PER_BLOCK 512   // TPB * 2
#define TILE_BYTES 38912      // 512 * 19 * 4

typedef unsigned long long u64;

__device__ int g_batch_is64;   // 1 if batch is int64, 0 if int32

struct CWPack {
    u64 w1p[40];    // {W1[c][k]}x2, index c*10+k
    u64 b1p[10];    // {b1[k]}x2
    u64 w2p[190];   // {W2[k][j]}x2 transposed, index j*10+k  (16B-aligned rows)
    u64 b2p[19];    // {b2[j]}x2
    u64 pad;
};

__device__ CWPack g_wscratch;      // staging (written by prep kernel)
__constant__ CWPack c_w;           // read-only broadcast copy

__device__ __forceinline__ u64 pack2(float lo, float hi) {
    u64 r;
    asm("mov.b64 %0, {%1, %2};" : "=l"(r) : "f"(lo), "f"(hi));
    return r;
}

__device__ __forceinline__ void unpack2(u64 v, float& lo, float& hi) {
    asm("mov.b64 {%0, %1}, %2;" : "=f"(lo), "=f"(hi) : "l"(v));
}

__device__ __forceinline__ u64 fma2(u64 a, u64 b, u64 c) {
    u64 d;
    asm("fma.rn.f32x2 %0, %1, %2, %3;" : "=l"(d) : "l"(a), "l"(b), "l"(c));
    return d;
}

__device__ __forceinline__ u64 relu2(u64 v) {
    float lo, hi;
    unpack2(v, lo, hi);
    lo = fmaxf(lo, 0.0f);
    hi = fmaxf(hi, 0.0f);
    return pack2(lo, hi);
}

// Build weight pack + detect batch dtype (int64 values 0..4095 -> all odd
// int32 words zero; 1024 random int32 in [0,4096) all-zero: impossible).
__global__ void prep_weights(const float* __restrict__ W1,
                             const float* __restrict__ b1,
                             const float* __restrict__ W2,
                             const float* __restrict__ b2,
                             const int*   __restrict__ b32)
{
    int t = threadIdx.x;
    if (t < 40)             g_wscratch.w1p[t]      = pack2(W1[t], W1[t]);
    if (t >= 64 && t < 74)  g_wscratch.b1p[t - 64] = pack2(b1[t - 64], b1[t - 64]);
    if (t >= 96 && t < 115) g_wscratch.b2p[t - 96] = pack2(b2[t - 96], b2[t - 96]);
    if (t < 190) {
        int j = t / 10, k = t - j * 10;   // transpose
        float w = W2[k * 19 + j];
        g_wscratch.w2p[t] = pack2(w, w);
    }
    if (t == 255) g_wscratch.pad = 0;

    if (t >= 192 && t < 224) {            // warp 6: parallel dtype scan
        int lane = t - 192;
        int bad = 0;
        #pragma unroll 4
        for (int i = 0; i < 32; i++)
            bad |= b32[1 + 2 * (lane * 32 + i)];
        unsigned any = __ballot_sync(0xffffffffu, bad != 0);
        if (lane == 0) g_batch_is64 = (any == 0) ? 1 : 0;
    }
}

__global__ __launch_bounds__(TPB, 3)
void edge_model_kernel(const float* __restrict__ src,
                       const float* __restrict__ dest,
                       const float* __restrict__ ea,
                       const float* __restrict__ u,
                       const void*  __restrict__ batch_raw,
                       float* __restrict__ out,        // [E,19]
                       long long E)
{
    __shared__ __align__(16) float otile[EDGES_PER_BLOCK * 19];  // 38912 B

    const int t = threadIdx.x;
    const int is64 = g_batch_is64;

    const long long base = (long long)blockIdx.x * EDGES_PER_BLOCK;

    if (base + EDGES_PER_BLOCK <= E) {
        // ============== fast path: full 512-edge block, 2 edges/thread ==============
        const long long p = (base >> 1) + t;   // pair index

        const float2 s = ((const float2*)src)[p];
        const float2 d = ((const float2*)dest)[p];
        const float2 a = ((const float2*)ea)[p];

        long long i0, i1;
        if (is64) {
            longlong2 bi = ((const longlong2*)batch_raw)[p];
            i0 = bi.x; i1 = bi.y;
        } else {
            int2 bi = ((const int2*)batch_raw)[p];
            i0 = bi.x; i1 = bi.y;
        }
        const float u0 = __ldg(&u[i0]);
        const float u1 = __ldg(&u[i1]);

        const u64 sp = pack2(s.x, s.y);
        const u64 dp = pack2(d.x, d.y);
        const u64 ap = pack2(a.x, a.y);
        const u64 up = pack2(u0, u1);

        // layer 1 (weights from constant bank — no L1 traffic)
        u64 h[10];
        #pragma unroll
        for (int k = 0; k < 10; k++) {
            u64 acc = c_w.b1p[k];
            acc = fma2(sp, c_w.w1p[k],      acc);
            acc = fma2(dp, c_w.w1p[10 + k], acc);
            acc = fma2(ap, c_w.w1p[20 + k], acc);
            acc = fma2(up, c_w.w1p[30 + k], acc);
            h[k] = relu2(acc);
        }

        // layer 2 into smem tile. Accs hold {edge0_j, edge1_j}; a 1-element
        // carry re-pairs them into (j-1, j) float2 stores per edge row:
        //   j odd : row0 pair at word 38t + (j-1)      (even -> 8B aligned)
        //   j even: row1 pair at word 38t + 19 + (j-1) (even -> 8B aligned)
        // u64 lane stride = 19 (odd) -> conflict-free.
        float* row0 = &otile[(2 * t)     * 19];
        float* row1 = &otile[(2 * t + 1) * 19];

        u64 prev;
        {   // j = 0
            u64 acc = c_w.b2p[0];
            const ulonglong2* wr = (const ulonglong2*)&c_w.w2p[0];
            #pragma unroll
            for (int kk = 0; kk < 5; kk++) {
                ulonglong2 w = wr[kk];
                acc = fma2(h[2 * kk],     w.x, acc);
                acc = fma2(h[2 * kk + 1], w.y, acc);
            }
            float lo, hi;
            unpack2(acc, lo, hi);
            row1[0] = hi;              // scalar leftover (1 instr)
            prev = acc;
        }
        #pragma unroll 2
        for (int j = 1; j < 19; j++) {
            u64 acc = c_w.b2p[j];
            const ulonglong2* wr = (const ulonglong2*)&c_w.w2p[j * 10];  // 16B aligned
            #pragma unroll
            for (int kk = 0; kk < 5; kk++) {
                ulonglong2 w = wr[kk];
                acc = fma2(h[2 * kk],     w.x, acc);
                acc = fma2(h[2 * kk + 1], w.y, acc);
            }
            float pl, ph, cl, ch;
            unpack2(prev, pl, ph);
            unpack2(acc,  cl, ch);
            if (j & 1) *(float2*)(row0 + j - 1) = make_float2(pl, cl);
            else       *(float2*)(row1 + j - 1) = make_float2(ph, ch);
            prev = acc;
        }
        {   // tail: row0[18]
            float lo, hi;
            unpack2(prev, lo, hi);
            row0[18] = lo;             // scalar leftover (1 instr)
        }
        __syncthreads();

        // One TMA bulk store flushes the whole tile.
        if (t == 0) {
            unsigned saddr = (unsigned)__cvta_generic_to_shared(otile);
            const float* g = out + base * 19;   // 16B-aligned
            asm volatile("fence.proxy.async.shared::cta;" ::: "memory");
            asm volatile(
                "cp.async.bulk.global.shared::cta.bulk_group [%0], [%1], %2;"
                :: "l"(g), "r"(saddr), "r"((unsigned)TILE_BYTES) : "memory");
            asm volatile("cp.async.bulk.commit_group;" ::: "memory");
            asm volatile("cp.async.bulk.wait_group 0;" ::: "memory");
        }
    } else {
        // ================= tail path (scalar, bounds-checked) =================
        for (long long e = base + t; e < E; e += TPB) {
            float x0 = src[e], x1 = dest[e], x2 = ea[e];
            long long bi = is64 ? ((const long long*)batch_raw)[e]
                                : (long long)((const int*)batch_raw)[e];
            float x3 = u[bi];
            float h[10];
            #pragma unroll
            for (int k = 0; k < 10; k++) {
                float lo, hiu;
                unpack2(c_w.w1p[k], lo, hiu);       float wa = lo;
                unpack2(c_w.w1p[10 + k], lo, hiu);  float wb = lo;
                unpack2(c_w.w1p[20 + k], lo, hiu);  float wc = lo;
                unpack2(c_w.w1p[30 + k], lo, hiu);  float wd = lo;
                unpack2(c_w.b1p[k], lo, hiu);
                float acc = lo;
                acc = fmaf(x0, wa, acc);
                acc = fmaf(x1, wb, acc);
                acc = fmaf(x2, wc, acc);
                acc = fmaf(x3, wd, acc);
                h[k] = fmaxf(acc, 0.0f);
            }
            #pragma unroll
            for (int j = 0; j < 19; j++) {
                float lo, hiu;
                unpack2(c_w.b2p[j], lo, hiu);
                float acc = lo;
                #pragma unroll
                for (int k = 0; k < 10; k++) {
                    unpack2(c_w.w2p[j * 10 + k], lo, hiu);
                    acc = fmaf(h[k], lo, acc);
                }
                out[e * 19 + j] = acc;
            }
        }
    }
}

extern "C" void kernel_launch(void* const* d_in, const int* in_sizes, int n_in,
                              void* d_out, int out_size)
{
    const float* src   = (const float*)d_in[0];
    const float* dest  = (const float*)d_in[1];
    const float* ea    = (const float*)d_in[2];
    const float* u     = (const float*)d_in[3];
    const void*  batch = d_in[4];
    const float* W1    = (const float*)d_in[5];
    const float* b1    = (const float*)d_in[6];
    const float* W2    = (const float*)d_in[7];
    const float* b2    = (const float*)d_in[8];
    float* out = (float*)d_out;

    const long long E = in_sizes[0];
    const int blocks = (int)((E + EDGES_PER_BLOCK - 1) / EDGES_PER_BLOCK);

    prep_weights<<<1, 256>>>(W1, b1, W2, b2, (const int*)batch);

    void* scratch_addr = nullptr;
    cudaGetSymbolAddress(&scratch_addr, g_wscratch);
    cudaMemcpyToSymbolAsync(c_w, scratch_addr, sizeof(CWPack), 0,
                            cudaMemcpyDeviceToDevice, 0);

    edge_model_kernel<<<blocks, TPB>>>(src, dest, ea, u, batch, out, E);
}